// round 8
// baseline (speedup 1.0000x reference)
#include <cuda_runtime.h>
#include <cuda_fp16.h>
#include <math.h>

#define Bb   512
#define Hh   256
#define Ld   256
#define Tt   64
#define Vv   128
#define NL   2
#define G    4
#define NTH  512

// ---------------- packed fp16 weights, block-streamable layout ----------------
// ATTN/COMB: 64 blocks; block s (4096B) = [lo: j=0..255 uint2 of W[j][s*4..s*4+3]]
//                                         [hi: j=0..255 uint2 of W[j][256+s*4..]]
// GRU layer: 64 blocks; block s (12288B) = [ih: col=0..767 uint2][hh: col=0..767 uint2]
// OUT: old layout (k4*128 + j)*4 + c, consumed via LDG.
#define OFF_ATTN 0          // 131072 halves
#define OFF_COMB 131072     // 131072
#define OFF_GRU  262144     // 2 x 393216
#define OFF_OUT  1048576    // 32768
#define PACK_TOTAL 1081344

__device__ __align__(16) __half g_pack[PACK_TOTAL];
__device__ __align__(16) __half g_enc[(size_t)Bb * Hh * Ld];

__global__ void pack_kernel(const float* __restrict__ aw, const float* __restrict__ cw,
                            const float* __restrict__ gih, const float* __restrict__ ghh,
                            const float* __restrict__ ow)
{
    int i = blockIdx.x * blockDim.x + threadIdx.x;
    if (i >= PACK_TOTAL) return;
    float v;
    if (i < 262144) {                        // attn or comb
        const float* W = (i < 131072) ? aw : cw;
        int r0 = i & 131071;
        int s  = r0 >> 11;                   // block
        int r  = r0 & 2047;
        int hs = r >> 10;                    // half select
        int rr = r & 1023;
        int j  = rr >> 2;
        int c  = rr & 3;
        v = W[j * 512 + hs * 256 + s * 4 + c];
    } else if (i < 1048576) {                // gru
        int i2 = i - 262144;
        int l  = i2 / 393216;
        int r  = i2 % 393216;
        int s  = r / 6144;
        int r2 = r % 6144;
        int hs = r2 / 3072;                  // 0=ih, 1=hh
        int r3 = r2 % 3072;
        int col = r3 >> 2;
        int c   = r3 & 3;
        const float* W = hs ? ghh : gih;
        v = W[l * 196608 + col * 256 + s * 4 + c];
    } else {                                 // out (old layout)
        int r = i - 1048576;
        int c = r & 3, j = (r >> 2) & 127, k4 = r >> 9;
        v = ow[j * 256 + k4 * 4 + c];
    }
    g_pack[i] = __float2half(v);
}

__global__ void pack_enc_kernel(const float* __restrict__ x)
{
    size_t i = (size_t)blockIdx.x * blockDim.x + threadIdx.x;
    float4 v = ((const float4*)x)[i];
    __half2 h0 = __floats2half2_rn(v.x, v.y);
    __half2 h1 = __floats2half2_rn(v.z, v.w);
    uint2 o;
    o.x = *(unsigned*)&h0;
    o.y = *(unsigned*)&h1;
    ((uint2*)g_enc)[i] = o;
}

// ---------------- f32x2 / fp16 helpers ----------------
typedef unsigned long long u64;

__device__ __forceinline__ void fma2(u64& d, u64 a, u64 b) {
    asm("fma.rn.f32x2 %0, %1, %2, %0;" : "+l"(d) : "l"(a), "l"(b));
}
__device__ __forceinline__ float sum2(u64 v) {
    return __uint_as_float((unsigned)v) + __uint_as_float((unsigned)(v >> 32));
}
__device__ __forceinline__ u64 cvt2(unsigned h) {
    float2 f = __half22float2(*(__half2*)&h);
    return ((u64)__float_as_uint(f.y) << 32) | (u64)__float_as_uint(f.x);
}

// ---------------- mbarrier / TMA bulk macros ----------------
#define MBINIT(a) asm volatile("mbarrier.init.shared.b64 [%0], 1;" :: "r"(a) : "memory")
#define MBEXPECT(a, bytes) \
    asm volatile("mbarrier.arrive.expect_tx.shared.b64 _, [%0], %1;" :: "r"(a), "r"(bytes) : "memory")
#define MBWAIT(a, ph) do { \
    unsigned _done = 0; \
    while (!_done) { \
        asm volatile("{\n\t.reg .pred P;\n\t" \
            "mbarrier.try_wait.parity.acquire.cta.shared::cta.b64 P, [%1], %2, 0x989680;\n\t" \
            "selp.b32 %0, 1, 0, P;\n\t}" \
            : "=r"(_done) : "r"(a), "r"(ph) : "memory"); \
    } \
} while (0)
#define TMA1D(dst, src, sz, mb) \
    asm volatile("cp.async.bulk.shared::cta.global.mbarrier::complete_tx::bytes [%0], [%1], %2, [%3];" \
        :: "r"(dst), "l"(src), "r"(sz), "r"(mb) : "memory")

// ---------------- block reduction (4 values, 16 warps) ----------------
__device__ __forceinline__ void block_reduce4(float v[G], float* sm, int tid, bool is_max) {
    __syncthreads();
    #pragma unroll
    for (int g = 0; g < G; g++) {
        #pragma unroll
        for (int o = 16; o > 0; o >>= 1) {
            float oth = __shfl_xor_sync(0xffffffffu, v[g], o);
            v[g] = is_max ? fmaxf(v[g], oth) : (v[g] + oth);
        }
    }
    int wid = tid >> 5;
    if ((tid & 31) == 0) {
        #pragma unroll
        for (int g = 0; g < G; g++) sm[wid * G + g] = v[g];
    }
    __syncthreads();
    #pragma unroll
    for (int g = 0; g < G; g++) {
        float r = sm[g];
        #pragma unroll
        for (int w = 1; w < 16; w++)
            r = is_max ? fmaxf(r, sm[w * G + g]) : (r + sm[w * G + g]);
        v[g] = r;
    }
}

// ---------------- dynamic smem layout (bytes) ----------------
#define SM_MBAR   0        // 16
#define SM_E      16       // 4096
#define SM_H      4112     // 8192
#define SM_AW     12304    // 4096
#define SM_APP    16400    // 4096
#define SM_X      20496    // 4096
#define SM_P2     24592    // 12288
#define SM_OUT    36880    // 16384
#define SM_RED    53264    // 256
#define SM_WB0    55296    // 49152
#define SM_WB1    104448   // 49152
#define SMEM_BYTES 153600

// ---------------- main persistent decoder kernel ----------------
__global__ __launch_bounds__(NTH)
void decoder_kernel(const int*   __restrict__ y,
                    const float* __restrict__ emb,
                    const float* __restrict__ attn_b,
                    const float* __restrict__ comb_b,
                    const float* __restrict__ gbi,
                    const float* __restrict__ gbh,
                    const float* __restrict__ out_b,
                    float* __restrict__ outp,
                    float* __restrict__ attnp)
{
    extern __shared__ __align__(1024) char dsm[];
    float* s_e   = (float*)(dsm + SM_E);
    float* s_h   = (float*)(dsm + SM_H);
    float* s_aw  = (float*)(dsm + SM_AW);
    float* s_app = (float*)(dsm + SM_APP);
    float* s_x   = (float*)(dsm + SM_X);
    float* s_p2  = (float*)(dsm + SM_P2);
    float* s_out = (float*)(dsm + SM_OUT);
    float* s_red = (float*)(dsm + SM_RED);
    const char* wbp[2] = { dsm + SM_WB0, dsm + SM_WB1 };

    const int tid  = threadIdx.x;
    const int wid  = tid >> 5;
    const int lane = tid & 31;
    const int jj   = tid & 255;
    const bool hi  = (tid >= 256);
    const int half = hi ? 1 : 0;
    const int b0   = blockIdx.x * G;

    const unsigned smem_base = (unsigned)__cvta_generic_to_shared(dsm);
    const unsigned mb0 = smem_base + SM_MBAR;
    const unsigned mb1 = smem_base + SM_MBAR + 8;
    const unsigned wbs[2] = { smem_base + SM_WB0, smem_base + SM_WB1 };
    const u64 gp = (u64)__cvta_generic_to_global(g_pack);
    const u64 srcA = gp + OFF_ATTN * 2;
    const u64 srcC = gp + OFF_COMB * 2;
    const u64 srcG = gp + OFF_GRU  * 2;

    int ph0 = 0, ph1 = 0;

    if (tid == 0) { MBINIT(mb0); MBINIT(mb1); }
    for (int i = tid; i < NL * G * Hh; i += NTH) s_h[i] = 0.f;
    __syncthreads();

    for (int t = 0; t < Tt; t++) {
        // prologue: attn chunk0 (weights independent of activations)
        if (tid == 0) { MBEXPECT(mb0, 32768u); TMA1D(wbs[0], srcA, 32768u, mb0); }

        // -------- embedding lookup --------
        #pragma unroll
        for (int i = tid; i < G * Hh; i += NTH) {
            int g = i >> 8, h = i & 255;
            int tok = (t == 0) ? 0 : y[(b0 + g) * Tt + t - 1];
            s_e[g * Hh + h] = emb[tok * Hh + h];
        }
        __syncthreads();

        // -------- attention scores: streamed, 8 chunks x 8 k4 --------
        {
            u64 acc[G] = {0, 0, 0, 0};
            const float* vb = hi ? s_h : s_e;
            for (int c = 0; c < 8; c++) {
                if (tid == 0 && c < 7) {
                    unsigned m = ((c + 1) & 1) ? mb1 : mb0;
                    MBEXPECT(m, 32768u);
                    TMA1D(wbs[(c + 1) & 1], srcA + (u64)(c + 1) * 32768u, 32768u, m);
                }
                if ((c & 1) == 0) { MBWAIT(mb0, ph0); ph0 ^= 1; }
                else              { MBWAIT(mb1, ph1); ph1 ^= 1; }
                const char* wp = wbp[c & 1] + half * 2048 + jj * 8;
                #pragma unroll
                for (int i = 0; i < 8; i++) {
                    uint2 wh = *(const uint2*)(wp + i * 4096);
                    u64 wx = cvt2(wh.x), wy = cvt2(wh.y);
                    int k4 = c * 8 + i;
                    #pragma unroll
                    for (int g = 0; g < G; g++) {
                        ulonglong2 xv = ((const ulonglong2*)(vb + g * Hh))[k4];
                        fma2(acc[g], wx, xv.x);
                        fma2(acc[g], wy, xv.y);
                    }
                }
                __syncthreads();
            }
            if (hi) {
                #pragma unroll
                for (int g = 0; g < G; g++) s_p2[(g * 3 + 0) * Hh + jj] = sum2(acc[g]);
            }
            __syncthreads();

            // softmax over L (true values in lo half)
            float sc[G];
            #pragma unroll
            for (int g = 0; g < G; g++)
                sc[g] = hi ? -1e30f : (sum2(acc[g]) + s_p2[(g * 3 + 0) * Hh + jj] + attn_b[jj]);
            float m[G];
            #pragma unroll
            for (int g = 0; g < G; g++) m[g] = sc[g];
            block_reduce4(m, s_red, tid, true);
            float p[G];
            #pragma unroll
            for (int g = 0; g < G; g++) p[g] = hi ? 0.f : __expf(sc[g] - m[g]);
            float s[G];
            #pragma unroll
            for (int g = 0; g < G; g++) s[g] = p[g];
            block_reduce4(s, s_red, tid, false);
            if (!hi) {
                #pragma unroll
                for (int g = 0; g < G; g++) {
                    float a = p[g] * (1.f / s[g]);
                    s_aw[g * Ld + jj] = a;
                    attnp[((size_t)(b0 + g) * Tt + t) * Ld + jj] = a;
                }
            }
            __syncthreads();
        }

        // prologue: comb chunk0 (overlaps einsum)
        if (tid == 0) { MBEXPECT(mb0, 32768u); TMA1D(wbs[0], srcC, 32768u, mb0); }

        // -------- applied = aw @ enc (fp16 enc) --------
        {
            const int g = wid >> 2;
            const int hbase = (wid & 3) * 64;
            const float4* awp = (const float4*)(s_aw + g * Ld);
            const float4 A0 = awp[lane * 2];
            const float4 A1 = awp[lane * 2 + 1];
            const uint4* xrow =
                (const uint4*)(g_enc + ((size_t)(b0 + g) * Hh + hbase) * Ld) + lane;
            #pragma unroll
            for (int it = 0; it < 64; it += 8) {
                uint4 xv[8];
                #pragma unroll
                for (int u = 0; u < 8; u++) xv[u] = xrow[(it + u) * 32];
                float d[8];
                #pragma unroll
                for (int u = 0; u < 8; u++) {
                    float2 f0 = __half22float2(*(__half2*)&xv[u].x);
                    float2 f1 = __half22float2(*(__half2*)&xv[u].y);
                    float2 f2 = __half22float2(*(__half2*)&xv[u].z);
                    float2 f3 = __half22float2(*(__half2*)&xv[u].w);
                    d[u] = f0.x * A0.x + f0.y * A0.y + f1.x * A0.z + f1.y * A0.w
                         + f2.x * A1.x + f2.y * A1.y + f3.x * A1.z + f3.y * A1.w;
                }
                #pragma unroll
                for (int u = 0; u < 8; u++) {
                    #pragma unroll
                    for (int o = 16; o > 0; o >>= 1)
                        d[u] += __shfl_xor_sync(0xffffffffu, d[u], o);
                }
                if (lane == 0) {
                    #pragma unroll
                    for (int u = 0; u < 8; u++) s_app[g * Hh + hbase + it + u] = d[u];
                }
            }
        }
        __syncthreads();

        // -------- combine: streamed, 8 chunks x 8 k4 --------
        {
            u64 acc[G] = {0, 0, 0, 0};
            const float* vb = hi ? s_e : s_app;
            for (int c = 0; c < 8; c++) {
                if (tid == 0 && c < 7) {
                    unsigned m = ((c + 1) & 1) ? mb1 : mb0;
                    MBEXPECT(m, 32768u);
                    TMA1D(wbs[(c + 1) & 1], srcC + (u64)(c + 1) * 32768u, 32768u, m);
                }
                if ((c & 1) == 0) { MBWAIT(mb0, ph0); ph0 ^= 1; }
                else              { MBWAIT(mb1, ph1); ph1 ^= 1; }
                const char* wp = wbp[c & 1] + half * 2048 + jj * 8;
                #pragma unroll
                for (int i = 0; i < 8; i++) {
                    uint2 wh = *(const uint2*)(wp + i * 4096);
                    u64 wx = cvt2(wh.x), wy = cvt2(wh.y);
                    int k4 = c * 8 + i;
                    #pragma unroll
                    for (int g = 0; g < G; g++) {
                        ulonglong2 xv = ((const ulonglong2*)(vb + g * Hh))[k4];
                        fma2(acc[g], wx, xv.x);
                        fma2(acc[g], wy, xv.y);
                    }
                }
                __syncthreads();
            }
            if (hi) {
                #pragma unroll
                for (int g = 0; g < G; g++) s_p2[(g * 3 + 0) * Hh + jj] = sum2(acc[g]);
            }
            __syncthreads();
            if (!hi) {
                const float bj = comb_b[jj];
                #pragma unroll
                for (int g = 0; g < G; g++)
                    s_x[g * Hh + jj] =
                        fmaxf(sum2(acc[g]) + s_p2[(g * 3 + 0) * Hh + jj] + bj, 0.f);
            }
            __syncthreads();
        }

        // -------- GRU layers: streamed, 16 chunks x 4 k4; lo=ih, hi=hh --------
        #pragma unroll
        for (int l = 0; l < NL; l++) {
            const u64 srcL = srcG + (u64)l * 786432u;   // 393216 halves * 2B
            if (tid == 0) { MBEXPECT(mb0, 49152u); TMA1D(wbs[0], srcL, 49152u, mb0); }
            u64 a0[G] = {0,0,0,0}, a1[G] = {0,0,0,0}, a2[G] = {0,0,0,0};
            const float* vb = hi ? (s_h + l * G * Hh) : s_x;
            for (int c = 0; c < 16; c++) {
                if (tid == 0 && c < 15) {
                    unsigned m = ((c + 1) & 1) ? mb1 : mb0;
                    MBEXPECT(m, 49152u);
                    TMA1D(wbs[(c + 1) & 1], srcL + (u64)(c + 1) * 49152u, 49152u, m);
                }
                if ((c & 1) == 0) { MBWAIT(mb0, ph0); ph0 ^= 1; }
                else              { MBWAIT(mb1, ph1); ph1 ^= 1; }
                const char* wp = wbp[c & 1] + half * 6144 + jj * 8;
                #pragma unroll
                for (int i = 0; i < 4; i++) {
                    const char* bp = wp + i * 12288;
                    uint2 wh0 = *(const uint2*)(bp);
                    uint2 wh1 = *(const uint2*)(bp + 2048);
                    uint2 wh2 = *(const uint2*)(bp + 4096);
                    u64 w0x = cvt2(wh0.x), w0y = cvt2(wh0.y);
                    u64 w1x = cvt2(wh1.x), w1y = cvt2(wh1.y);
                    u64 w2x = cvt2(wh2.x), w2y = cvt2(wh2.y);
                    int k4 = c * 4 + i;
                    #pragma unroll
                    for (int g = 0; g < G; g++) {
                        ulonglong2 xv = ((const ulonglong2*)(vb + g * Hh))[k4];
                        fma2(a0[g], w0x, xv.x); fma2(a0[g], w0y, xv.y);
                        fma2(a1[g], w1x, xv.x); fma2(a1[g], w1y, xv.y);
                        fma2(a2[g], w2x, xv.x); fma2(a2[g], w2y, xv.y);
                    }
                }
                __syncthreads();
            }
            if (hi) {
                #pragma unroll
                for (int g = 0; g < G; g++) {
                    s_p2[(g * 3 + 0) * Hh + jj] = sum2(a0[g]);
                    s_p2[(g * 3 + 1) * Hh + jj] = sum2(a1[g]);
                    s_p2[(g * 3 + 2) * Hh + jj] = sum2(a2[g]);
                }
            }
            __syncthreads();
            if (!hi) {
                const float bi0 = gbi[l * 768 + jj];
                const float bi1 = gbi[l * 768 + 256 + jj];
                const float bi2 = gbi[l * 768 + 512 + jj];
                const float bh0 = gbh[l * 768 + jj];
                const float bh1 = gbh[l * 768 + 256 + jj];
                const float bh2 = gbh[l * 768 + 512 + jj];
                #pragma unroll
                for (int g = 0; g < G; g++) {
                    float hprev = s_h[(l * G + g) * Hh + jj];
                    float i0 = sum2(a0[g]) + bi0, h0 = s_p2[(g * 3 + 0) * Hh + jj] + bh0;
                    float i1 = sum2(a1[g]) + bi1, h1 = s_p2[(g * 3 + 1) * Hh + jj] + bh1;
                    float i2 = sum2(a2[g]) + bi2, h2 = s_p2[(g * 3 + 2) * Hh + jj] + bh2;
                    float r = 1.f / (1.f + __expf(-(i0 + h0)));
                    float z = 1.f / (1.f + __expf(-(i1 + h1)));
                    float n = tanhf(i2 + r * h2);
                    float hn = (1.f - z) * n + z * hprev;
                    s_h[(l * G + g) * Hh + jj] = hn;
                    s_x[g * Hh + jj]           = hn;
                }
            }
            __syncthreads();
        }

        // -------- output projection (LDG path) + log_softmax --------
        {
            int j  = tid & 127;
            int sl = tid >> 7;
            u64 acc[G] = {0, 0, 0, 0};
            const uint2* W = (const uint2*)(g_pack + OFF_OUT) + j;
            #pragma unroll 8
            for (int k4 = sl * 16; k4 < sl * 16 + 16; k4++) {
                uint2 wh = W[k4 * 128];
                u64 wx = cvt2(wh.x), wy = cvt2(wh.y);
                #pragma unroll
                for (int g = 0; g < G; g++) {
                    ulonglong2 hv = ((const ulonglong2*)(s_x + g * Hh))[k4];
                    fma2(acc[g], wx, hv.x);
                    fma2(acc[g], wy, hv.y);
                }
            }
            float* s_op = s_p2;     // [G][4][128] = 2048 <= 3072 floats
            #pragma unroll
            for (int g = 0; g < G; g++) s_op[(g * 4 + sl) * 128 + j] = sum2(acc[g]);
            __syncthreads();

            float oacc[G];
            #pragma unroll
            for (int g = 0; g < G; g++) {
                oacc[g] = (tid < 128)
                    ? (out_b[j] + s_op[(g * 4 + 0) * 128 + j] + s_op[(g * 4 + 1) * 128 + j]
                               + s_op[(g * 4 + 2) * 128 + j] + s_op[(g * 4 + 3) * 128 + j])
                    : -1e30f;
            }
            float m[G];
            #pragma unroll
            for (int g = 0; g < G; g++) m[g] = oacc[g];
            block_reduce4(m, s_red, tid, true);
            float p[G];
            #pragma unroll
            for (int g = 0; g < G; g++) p[g] = (tid < 128) ? __expf(oacc[g] - m[g]) : 0.f;
            float s[G];
            #pragma unroll
            for (int g = 0; g < G; g++) s[g] = p[g];
            block_reduce4(s, s_red, tid, false);
            if (tid < 128) {
                #pragma unroll
                for (int g = 0; g < G; g++)
                    s_out[(g * Vv + j) * 8 + (t & 7)] = oacc[g] - m[g] - logf(s[g]);
            }
        }

        // -------- flush staged outputs every 8 steps --------
        __syncthreads();
        if ((t & 7) == 7) {
            int g = tid >> 7, j = tid & 127;
            float4 v0 = *(float4*)&s_out[(g * Vv + j) * 8 + 0];
            float4 v1 = *(float4*)&s_out[(g * Vv + j) * 8 + 4];
            float4* dst = (float4*)(outp + ((size_t)(b0 + g) * Vv + j) * Tt + (t - 7));
            dst[0] = v0;
            dst[1] = v1;
            __syncthreads();
        }
    }
}

// ---------------- launch ----------------
extern "C" void kernel_launch(void* const* d_in, const int* in_sizes, int n_in,
                              void* d_out, int out_size)
{
    const float* x      = (const float*)d_in[0];
    const int*   y      = (const int*)  d_in[1];
    const float* emb    = (const float*)d_in[2];
    const float* attn_w = (const float*)d_in[3];
    const float* attn_b = (const float*)d_in[4];
    const float* comb_w = (const float*)d_in[5];
    const float* comb_b = (const float*)d_in[6];
    const float* gih    = (const float*)d_in[7];
    const float* ghh    = (const float*)d_in[8];
    const float* gbi    = (const float*)d_in[9];
    const float* gbh    = (const float*)d_in[10];
    const float* out_w  = (const float*)d_in[11];
    const float* out_b  = (const float*)d_in[12];

    float* outp  = (float*)d_out;
    float* attnp = (float*)d_out + (size_t)Bb * Vv * Tt;

    cudaFuncSetAttribute(decoder_kernel,
                         cudaFuncAttributeMaxDynamicSharedMemorySize, SMEM_BYTES);

    pack_kernel<<<(PACK_TOTAL + 255) / 256, 256>>>(attn_w, comb_w, gih, ghh, out_w);
    pack_enc_kernel<<<((size_t)Bb * Hh * Ld / 4 + 255) / 256, 256>>>(x);
    decoder_kernel<<<Bb / G, NTH, SMEM_BYTES>>>(y, emb, attn_b, comb_b, gbi, gbh,
                                                out_b, outp, attnp);
}

// round 9
// speedup vs baseline: 1.0546x; 1.0546x over previous
#include <cuda_runtime.h>
#include <cuda_fp16.h>
#include <math.h>

#define Bb   512
#define Hh   256
#define Ld   256
#define Tt   64
#define Vv   128
#define NL   2
#define G    4
#define NTH  512

// ---------------- packed fp16 weight scratch (transposed + k-interleaved) ------------
// P[(k4*N + j)*4 + c] = W[j*K + 4*k4 + c]; element type is __half (uint2 per 4 k).
#define OFF_ATTN 0          // 512x256  -> 131072
#define OFF_COMB 131072     // 512x256  -> 131072
#define OFF_GIH  262144     // 2 x 256x768 -> 393216
#define OFF_GHH  655360     // 2 x 256x768 -> 393216
#define OFF_OUT  1048576    // 256x128  -> 32768
#define PACK_TOTAL 1081344

#define PACK_BLOCKS 4224            // ceil(PACK_TOTAL/256)
#define ENC_BLOCKS  32768           // (512*256*256/4)/256

__device__ __align__(16) __half g_pack[PACK_TOTAL];
__device__ __align__(16) __half g_enc[(size_t)Bb * Hh * Ld];   // fp16 encoder memory

// merged pack: weights (first PACK_BLOCKS blocks) + encoder fp16 (rest)
__global__ void pack_all_kernel(const float* __restrict__ aw, const float* __restrict__ cw,
                                const float* __restrict__ gih, const float* __restrict__ ghh,
                                const float* __restrict__ ow, const float* __restrict__ x)
{
    if (blockIdx.x < PACK_BLOCKS) {
        int i = blockIdx.x * blockDim.x + threadIdx.x;
        if (i >= PACK_TOTAL) return;
        float v;
        if (i < 131072) {                       // attn: K=512, N=256
            int c = i & 3, j = (i >> 2) & 255, k4 = i >> 10;
            v = aw[j * 512 + k4 * 4 + c];
        } else if (i < 262144) {                // comb: K=512, N=256
            int r = i - 131072;
            int c = r & 3, j = (r >> 2) & 255, k4 = r >> 10;
            v = cw[j * 512 + k4 * 4 + c];
        } else if (i < 655360) {                // gru ih: per layer K=256, N=768
            int r = i - 262144;
            int layer = r / 196608; int q = r % 196608;
            int c = q & 3; int t2 = q >> 2; int j = t2 % 768; int k4 = t2 / 768;
            v = gih[layer * 196608 + j * 256 + k4 * 4 + c];
        } else if (i < 1048576) {               // gru hh
            int r = i - 655360;
            int layer = r / 196608; int q = r % 196608;
            int c = q & 3; int t2 = q >> 2; int j = t2 % 768; int k4 = t2 / 768;
            v = ghh[layer * 196608 + j * 256 + k4 * 4 + c];
        } else {                                // out: K=256, N=128
            int r = i - 1048576;
            int c = r & 3, j = (r >> 2) & 127, k4 = r >> 9;
            v = ow[j * 256 + k4 * 4 + c];
        }
        g_pack[i] = __float2half(v);
    } else {
        size_t i = (size_t)(blockIdx.x - PACK_BLOCKS) * blockDim.x + threadIdx.x;
        float4 v = ((const float4*)x)[i];
        __half2 h0 = __floats2half2_rn(v.x, v.y);
        __half2 h1 = __floats2half2_rn(v.z, v.w);
        uint2 o;
        o.x = *(unsigned*)&h0;
        o.y = *(unsigned*)&h1;
        ((uint2*)g_enc)[i] = o;
    }
}

// ---------------- f32x2 packed math helpers (sm_10x FFMA2) ----------------
typedef unsigned long long u64;

__device__ __forceinline__ void fma2(u64& d, u64 a, u64 b) {
    asm("fma.rn.f32x2 %0, %1, %2, %0;" : "+l"(d) : "l"(a), "l"(b));
}
__device__ __forceinline__ float sum2(u64 v) {
    return __uint_as_float((unsigned)v) + __uint_as_float((unsigned)(v >> 32));
}
// fp16x2 -> packed f32x2 (lo half -> low word)
__device__ __forceinline__ u64 cvt2(unsigned h) {
    float2 f = __half22float2(*(__half2*)&h);
    return ((u64)__float_as_uint(f.y) << 32) | (u64)__float_as_uint(f.x);
}

// ---------------- main persistent decoder kernel ----------------
__global__ __launch_bounds__(NTH)
void decoder_kernel(const int*   __restrict__ y,      // [B,T]
                    const float* __restrict__ emb,    // [V,H]
                    const float* __restrict__ attn_b, // [L]
                    const float* __restrict__ comb_b, // [H]
                    const float* __restrict__ gbi,    // [2,768]
                    const float* __restrict__ gbh,    // [2,768]
                    const float* __restrict__ out_b,  // [V]
                    float* __restrict__ outp,         // [B,V,T]
                    float* __restrict__ attnp)        // [B,T,L]
{
    __shared__ __align__(16) float s_e  [G][Hh];
    __shared__ __align__(16) float s_h  [NL][G][Hh];
    __shared__ __align__(16) float s_aw [G][Ld];
    __shared__ __align__(16) float s_app[G][Hh];
    __shared__ __align__(16) float s_x  [G][Hh];
    __shared__ __align__(16) float s_p2 [G][3][Hh];
    __shared__ __align__(16) float s_out[G][Vv][8];

    const int tid  = threadIdx.x;
    const int wid  = tid >> 5;
    const int lane = tid & 31;
    const int jj   = tid & 255;
    const bool hi  = (tid >= 256);
    const int b0   = blockIdx.x * G;

    const __half* Pattn = g_pack + OFF_ATTN;
    const __half* Pcomb = g_pack + OFF_COMB;
    const __half* Pgih  = g_pack + OFF_GIH;
    const __half* Pghh  = g_pack + OFF_GHH;
    const __half* Pout  = g_pack + OFF_OUT;

    for (int i = tid; i < NL * G * Hh; i += NTH)
        (&s_h[0][0][0])[i] = 0.f;
    __syncthreads();

    for (int t = 0; t < Tt; t++) {
        // -------- embedding lookup (teacher forcing; SOS=0 at t=0) --------
        #pragma unroll
        for (int i = tid; i < G * Hh; i += NTH) {
            int g = i >> 8, h = i & 255;
            int tok = (t == 0) ? 0 : y[(b0 + g) * Tt + t - 1];
            s_e[g][h] = emb[tok * Hh + h];
        }
        __syncthreads();

        // -------- attention scores: lo half = e-part, hi half = h-part --------
        {
            u64 acc[G] = {0, 0, 0, 0};
            const uint2* W = (const uint2*)Pattn + (hi ? 64 * 256 : 0) + jj;
            const float* vb = hi ? &s_h[0][0][0] : &s_e[0][0];
            #pragma unroll 8
            for (int k4 = 0; k4 < 64; k4++) {
                uint2 wh = W[k4 * 256];
                u64 wx = cvt2(wh.x), wy = cvt2(wh.y);
                #pragma unroll
                for (int g = 0; g < G; g++) {
                    ulonglong2 xv = ((const ulonglong2*)(vb + g * Hh))[k4];
                    fma2(acc[g], wx, xv.x);
                    fma2(acc[g], wy, xv.y);
                }
            }
            if (hi) {
                #pragma unroll
                for (int g = 0; g < G; g++) s_p2[g][0][jj] = sum2(acc[g]);
            }
            __syncthreads();
            if (!hi) {
                const float ab = attn_b[jj];
                #pragma unroll
                for (int g = 0; g < G; g++)
                    s_p2[g][1][jj] = sum2(acc[g]) + s_p2[g][0][jj] + ab;
            }
            __syncthreads();

            // warp-per-row softmax over L=256 (warps 0..3, no block barriers inside)
            if (wid < 4) {
                const int g = wid;
                float sc[8];
                #pragma unroll
                for (int i = 0; i < 8; i++) sc[i] = s_p2[g][1][i * 32 + lane];
                float m = sc[0];
                #pragma unroll
                for (int i = 1; i < 8; i++) m = fmaxf(m, sc[i]);
                #pragma unroll
                for (int o = 16; o > 0; o >>= 1)
                    m = fmaxf(m, __shfl_xor_sync(0xffffffffu, m, o));
                float p[8], s = 0.f;
                #pragma unroll
                for (int i = 0; i < 8; i++) { p[i] = __expf(sc[i] - m); s += p[i]; }
                #pragma unroll
                for (int o = 16; o > 0; o >>= 1)
                    s += __shfl_xor_sync(0xffffffffu, s, o);
                float inv = 1.f / s;
                float* ap = attnp + ((size_t)(b0 + g) * Tt + t) * Ld;
                #pragma unroll
                for (int i = 0; i < 8; i++) {
                    float a = p[i] * inv;
                    s_aw[g][i * 32 + lane] = a;
                    ap[i * 32 + lane] = a;
                }
            }
            __syncthreads();
        }

        // -------- applied = aw @ enc (fp16 enc, warp owns fixed row g) --------
        {
            const int g = wid >> 2;                    // 4 warps per batch row
            const int hbase = (wid & 3) * 64;          // 64 h-values per warp
            const float4* awp = (const float4*)(s_aw[g]);
            const float4 A0 = awp[lane * 2];
            const float4 A1 = awp[lane * 2 + 1];
            const uint4* xrow =
                (const uint4*)(g_enc + ((size_t)(b0 + g) * Hh + hbase) * Ld) + lane;
            #pragma unroll
            for (int it = 0; it < 64; it += 8) {
                uint4 xv[8];
                #pragma unroll
                for (int u = 0; u < 8; u++) xv[u] = xrow[(it + u) * 32];
                float d[8];
                #pragma unroll
                for (int u = 0; u < 8; u++) {
                    float2 f0 = __half22float2(*(__half2*)&xv[u].x);
                    float2 f1 = __half22float2(*(__half2*)&xv[u].y);
                    float2 f2 = __half22float2(*(__half2*)&xv[u].z);
                    float2 f3 = __half22float2(*(__half2*)&xv[u].w);
                    d[u] = f0.x * A0.x + f0.y * A0.y + f1.x * A0.z + f1.y * A0.w
                         + f2.x * A1.x + f2.y * A1.y + f3.x * A1.z + f3.y * A1.w;
                }
                #pragma unroll
                for (int u = 0; u < 8; u++) {
                    #pragma unroll
                    for (int o = 16; o > 0; o >>= 1)
                        d[u] += __shfl_xor_sync(0xffffffffu, d[u], o);
                }
                if (lane == 0) {
                    #pragma unroll
                    for (int u = 0; u < 8; u++) s_app[g][hbase + it + u] = d[u];
                }
            }
        }
        __syncthreads();

        // -------- combine: lo half = applied-part, hi half = e-part --------
        {
            u64 acc[G] = {0, 0, 0, 0};
            const uint2* W = (const uint2*)Pcomb + (hi ? 64 * 256 : 0) + jj;
            const float* vb = hi ? &s_e[0][0] : &s_app[0][0];
            #pragma unroll 8
            for (int k4 = 0; k4 < 64; k4++) {
                uint2 wh = W[k4 * 256];
                u64 wx = cvt2(wh.x), wy = cvt2(wh.y);
                #pragma unroll
                for (int g = 0; g < G; g++) {
                    ulonglong2 xv = ((const ulonglong2*)(vb + g * Hh))[k4];
                    fma2(acc[g], wx, xv.x);
                    fma2(acc[g], wy, xv.y);
                }
            }
            if (hi) {
                #pragma unroll
                for (int g = 0; g < G; g++) s_p2[g][0][jj] = sum2(acc[g]);
            }
            __syncthreads();
            if (!hi) {
                const float bj = comb_b[jj];
                #pragma unroll
                for (int g = 0; g < G; g++)
                    s_x[g][jj] = fmaxf(sum2(acc[g]) + s_p2[g][0][jj] + bj, 0.f);
            }
            __syncthreads();
        }

        // -------- GRU layers: lo half = ih matvec, hi half = hh matvec --------
        #pragma unroll
        for (int l = 0; l < NL; l++) {
            u64 a0[G] = {0,0,0,0}, a1[G] = {0,0,0,0}, a2[G] = {0,0,0,0};
            const uint2* W =
                (const uint2*)((hi ? Pghh : Pgih) + l * 196608) + jj;
            const float* vb = hi ? &s_h[l][0][0] : &s_x[0][0];
            #pragma unroll 4
            for (int k4 = 0; k4 < 64; k4++) {
                uint2 wh0 = W[k4 * 768];
                uint2 wh1 = W[k4 * 768 + 256];
                uint2 wh2 = W[k4 * 768 + 512];
                u64 w0x = cvt2(wh0.x), w0y = cvt2(wh0.y);
                u64 w1x = cvt2(wh1.x), w1y = cvt2(wh1.y);
                u64 w2x = cvt2(wh2.x), w2y = cvt2(wh2.y);
                #pragma unroll
                for (int g = 0; g < G; g++) {
                    ulonglong2 xv = ((const ulonglong2*)(vb + g * Hh))[k4];
                    fma2(a0[g], w0x, xv.x); fma2(a0[g], w0y, xv.y);
                    fma2(a1[g], w1x, xv.x); fma2(a1[g], w1y, xv.y);
                    fma2(a2[g], w2x, xv.x); fma2(a2[g], w2y, xv.y);
                }
            }
            if (hi) {
                #pragma unroll
                for (int g = 0; g < G; g++) {
                    s_p2[g][0][jj] = sum2(a0[g]);
                    s_p2[g][1][jj] = sum2(a1[g]);
                    s_p2[g][2][jj] = sum2(a2[g]);
                }
            }
            __syncthreads();
            if (!hi) {
                const float bi0 = gbi[l * 768 + jj];
                const float bi1 = gbi[l * 768 + 256 + jj];
                const float bi2 = gbi[l * 768 + 512 + jj];
                const float bh0 = gbh[l * 768 + jj];
                const float bh1 = gbh[l * 768 + 256 + jj];
                const float bh2 = gbh[l * 768 + 512 + jj];
                #pragma unroll
                for (int g = 0; g < G; g++) {
                    float hprev = s_h[l][g][jj];
                    float i0 = sum2(a0[g]) + bi0, h0 = s_p2[g][0][jj] + bh0;
                    float i1 = sum2(a1[g]) + bi1, h1 = s_p2[g][1][jj] + bh1;
                    float i2 = sum2(a2[g]) + bi2, h2 = s_p2[g][2][jj] + bh2;
                    float r = 1.f / (1.f + __expf(-(i0 + h0)));
                    float z = 1.f / (1.f + __expf(-(i1 + h1)));
                    float n = tanhf(i2 + r * h2);
                    float hn = (1.f - z) * n + z * hprev;
                    s_h[l][g][jj] = hn;
                    s_x[g][jj]    = hn;
                }
            }
            __syncthreads();
        }

        // -------- output projection (K split 4 ways) + warp-per-row log_softmax ------
        {
            int j  = tid & 127;
            int sl = tid >> 7;
            u64 acc[G] = {0, 0, 0, 0};
            const uint2* W = (const uint2*)Pout + j;
            #pragma unroll 8
            for (int k4 = sl * 16; k4 < sl * 16 + 16; k4++) {
                uint2 wh = W[k4 * 128];
                u64 wx = cvt2(wh.x), wy = cvt2(wh.y);
                #pragma unroll
                for (int g = 0; g < G; g++) {
                    ulonglong2 hv = ((const ulonglong2*)s_x[g])[k4];
                    fma2(acc[g], wx, hv.x);
                    fma2(acc[g], wy, hv.y);
                }
            }
            float* s_op = &s_p2[0][0][0];
            #pragma unroll
            for (int g = 0; g < G; g++) s_op[(g * 4 + sl) * 128 + j] = sum2(acc[g]);
            __syncthreads();

            if (wid < 4) {
                const int g = wid;
                float o[4];
                #pragma unroll
                for (int i = 0; i < 4; i++) {
                    int j2 = i * 32 + lane;
                    o[i] = out_b[j2]
                         + s_op[(g * 4 + 0) * 128 + j2] + s_op[(g * 4 + 1) * 128 + j2]
                         + s_op[(g * 4 + 2) * 128 + j2] + s_op[(g * 4 + 3) * 128 + j2];
                }
                float m = fmaxf(fmaxf(o[0], o[1]), fmaxf(o[2], o[3]));
                #pragma unroll
                for (int ofs = 16; ofs > 0; ofs >>= 1)
                    m = fmaxf(m, __shfl_xor_sync(0xffffffffu, m, ofs));
                float s = 0.f;
                #pragma unroll
                for (int i = 0; i < 4; i++) s += __expf(o[i] - m);
                #pragma unroll
                for (int ofs = 16; ofs > 0; ofs >>= 1)
                    s += __shfl_xor_sync(0xffffffffu, s, ofs);
                float mls = m + logf(s);
                #pragma unroll
                for (int i = 0; i < 4; i++)
                    s_out[g][i * 32 + lane][t & 7] = o[i] - mls;
            }
        }

        // -------- flush staged outputs every 8 steps (coalesced float4 x2) --------
        __syncthreads();
        if ((t & 7) == 7) {
            int g = tid >> 7, j = tid & 127;
            float4 v0 = *(float4*)&s_out[g][j][0];
            float4 v1 = *(float4*)&s_out[g][j][4];
            float4* dst = (float4*)(outp + ((size_t)(b0 + g) * Vv + j) * Tt + (t - 7));
            dst[0] = v0;
            dst[1] = v1;
            __syncthreads();
        }
    }
}

// ---------------- launch ----------------
extern "C" void kernel_launch(void* const* d_in, const int* in_sizes, int n_in,
                              void* d_out, int out_size)
{
    const float* x      = (const float*)d_in[0];
    const int*   y      = (const int*)  d_in[1];
    const float* emb    = (const float*)d_in[2];
    const float* attn_w = (const float*)d_in[3];
    const float* attn_b = (const float*)d_in[4];
    const float* comb_w = (const float*)d_in[5];
    const float* comb_b = (const float*)d_in[6];
    const float* gih    = (const float*)d_in[7];
    const float* ghh    = (const float*)d_in[8];
    const float* gbi    = (const float*)d_in[9];
    const float* gbh    = (const float*)d_in[10];
    const float* out_w  = (const float*)d_in[11];
    const float* out_b  = (const float*)d_in[12];

    float* outp  = (float*)d_out;                        // [B,V,T]
    float* attnp = (float*)d_out + (size_t)Bb * Vv * Tt; // [B,T,L]

    pack_all_kernel<<<PACK_BLOCKS + ENC_BLOCKS, 256>>>(attn_w, comb_w, gih, ghh, out_w, x);
    decoder_kernel<<<Bb / G, NTH>>>(y, emb, attn_b, comb_b, gbi, gbh, out_b, outp, attnp);
}

// round 10
// speedup vs baseline: 1.3363x; 1.2671x over previous
#include <cuda_runtime.h>
#include <cuda_fp16.h>
#include <math.h>

#define Bb   512
#define Hh   256
#define Ld   256
#define Tt   64
#define Vv   128
#define NL   2
#define G    4
#define NTH  512

// ---------------- packed fp16 weight scratch (transposed + k-interleaved) ------------
// P[(k4*N + j)*4 + c] = W[j*K_src + off + k4*4 + c]; element = __half (uint2 per 4 k).
// attn/comb now store only their K=256 dynamic halves (h-part / applied-part).
#define OFF_ATTNH 0         // attn h-part: K=256,N=256 -> 65536
#define OFF_COMBA 65536     // comb applied-part:       -> 65536
#define OFF_GIH   131072    // 2 x 256x768 -> 393216
#define OFF_GHH   524288    // 2 x 256x768 -> 393216
#define OFF_OUT   917504    // 256x128 -> 32768
#define PACK_TOTAL 950272

#define PACK_BLOCKS 3712            // ceil(PACK_TOTAL/256)
#define ENC_BLOCKS  32768           // (512*256*256/4)/256

__device__ __align__(16) __half g_pack[PACK_TOTAL];
__device__ __align__(16) __half g_enc[(size_t)Bb * Hh * Ld];   // fp16 encoder memory
__device__ __align__(16) float  g_Tattn[Vv * Ld];              // emb@attn_w_e^T + attn_b
__device__ __align__(16) float  g_Tcomb[Vv * Hh];              // emb@comb_w_e^T + comb_b

// merged pack: weights (first PACK_BLOCKS blocks) + encoder fp16 (rest)
__global__ void pack_all_kernel(const float* __restrict__ aw, const float* __restrict__ cw,
                                const float* __restrict__ gih, const float* __restrict__ ghh,
                                const float* __restrict__ ow, const float* __restrict__ x)
{
    if (blockIdx.x < PACK_BLOCKS) {
        int i = blockIdx.x * blockDim.x + threadIdx.x;
        if (i >= PACK_TOTAL) return;
        float v;
        if (i < 65536) {                        // attn h-part: W[j][256 + k]
            int c = i & 3, j = (i >> 2) & 255, k4 = i >> 10;
            v = aw[j * 512 + 256 + k4 * 4 + c];
        } else if (i < 131072) {                // comb applied-part: W[j][k]
            int r = i - 65536;
            int c = r & 3, j = (r >> 2) & 255, k4 = r >> 10;
            v = cw[j * 512 + k4 * 4 + c];
        } else if (i < 524288) {                // gru ih: per layer K=256, N=768
            int r = i - 131072;
            int layer = r / 196608; int q = r % 196608;
            int c = q & 3; int t2 = q >> 2; int j = t2 % 768; int k4 = t2 / 768;
            v = gih[layer * 196608 + j * 256 + k4 * 4 + c];
        } else if (i < 917504) {                // gru hh
            int r = i - 524288;
            int layer = r / 196608; int q = r % 196608;
            int c = q & 3; int t2 = q >> 2; int j = t2 % 768; int k4 = t2 / 768;
            v = ghh[layer * 196608 + j * 256 + k4 * 4 + c];
        } else {                                // out: K=256, N=128
            int r = i - 917504;
            int c = r & 3, j = (r >> 2) & 127, k4 = r >> 9;
            v = ow[j * 256 + k4 * 4 + c];
        }
        g_pack[i] = __float2half(v);
    } else {
        size_t i = (size_t)(blockIdx.x - PACK_BLOCKS) * blockDim.x + threadIdx.x;
        float4 v = ((const float4*)x)[i];
        __half2 h0 = __floats2half2_rn(v.x, v.y);
        __half2 h1 = __floats2half2_rn(v.z, v.w);
        uint2 o;
        o.x = *(unsigned*)&h0;
        o.y = *(unsigned*)&h1;
        ((uint2*)g_enc)[i] = o;
    }
}

// precompute token tables: T_attn[tok][l] (bias baked), T_comb[tok][j] (bias baked), fp32
__global__ void precompute_tok_kernel(const float* __restrict__ emb,
                                      const float* __restrict__ aw, const float* __restrict__ ab,
                                      const float* __restrict__ cw, const float* __restrict__ cb)
{
    __shared__ float se[Hh];
    int tok = blockIdx.x & 127;
    bool isComb = blockIdx.x >= 128;
    int j = threadIdx.x;                 // 256 threads: output column
    se[j] = emb[tok * Hh + j];
    __syncthreads();
    const float* W = isComb ? (cw + j * 512 + 256) : (aw + j * 512);
    float s = 0.f;
    #pragma unroll 8
    for (int k = 0; k < 256; k++) s += W[k] * se[k];
    if (isComb) g_Tcomb[tok * Hh + j] = s + cb[j];
    else        g_Tattn[tok * Ld + j] = s + ab[j];
}

// ---------------- f32x2 packed math helpers (sm_10x FFMA2) ----------------
typedef unsigned long long u64;

__device__ __forceinline__ void fma2(u64& d, u64 a, u64 b) {
    asm("fma.rn.f32x2 %0, %1, %2, %0;" : "+l"(d) : "l"(a), "l"(b));
}
__device__ __forceinline__ float sum2(u64 v) {
    return __uint_as_float((unsigned)v) + __uint_as_float((unsigned)(v >> 32));
}
__device__ __forceinline__ u64 cvt2(unsigned h) {
    float2 f = __half22float2(*(__half2*)&h);
    return ((u64)__float_as_uint(f.y) << 32) | (u64)__float_as_uint(f.x);
}

// ---------------- vectorized block reduction (4 values, 16 warps) ----------------
__device__ __forceinline__ void block_reduce4(float v[G], float* sm, int tid, bool is_max) {
    __syncthreads();
    #pragma unroll
    for (int g = 0; g < G; g++) {
        #pragma unroll
        for (int o = 16; o > 0; o >>= 1) {
            float oth = __shfl_xor_sync(0xffffffffu, v[g], o);
            v[g] = is_max ? fmaxf(v[g], oth) : (v[g] + oth);
        }
    }
    int wid = tid >> 5;
    if ((tid & 31) == 0) {
        #pragma unroll
        for (int g = 0; g < G; g++) sm[wid * G + g] = v[g];
    }
    __syncthreads();
    #pragma unroll
    for (int g = 0; g < G; g++) {
        float r = sm[g];
        #pragma unroll
        for (int w = 1; w < 16; w++)
            r = is_max ? fmaxf(r, sm[w * G + g]) : (r + sm[w * G + g]);
        v[g] = r;
    }
}

// ---------------- main persistent decoder kernel (R7 structure + token tables) -------
__global__ __launch_bounds__(NTH)
void decoder_kernel(const int*   __restrict__ y,      // [B,T]
                    const float* __restrict__ gbi,    // [2,768]
                    const float* __restrict__ gbh,    // [2,768]
                    const float* __restrict__ out_b,  // [V]
                    float* __restrict__ outp,         // [B,V,T]
                    float* __restrict__ attnp)        // [B,T,L]
{
    __shared__ __align__(16) float s_h  [NL][G][Hh];
    __shared__ __align__(16) float s_aw [G][Ld];
    __shared__ __align__(16) float s_app[G][Hh];
    __shared__ __align__(16) float s_x  [G][Hh];
    __shared__ __align__(16) float s_p2 [G][3][Hh];
    __shared__ __align__(16) float s_out[G][Vv][8];
    __shared__ float s_red[16 * G];
    __shared__ int   s_tok[G];

    const int tid  = threadIdx.x;
    const int wid  = tid >> 5;
    const int lane = tid & 31;
    const int jj   = tid & 255;
    const bool hi  = (tid >= 256);
    const int b0   = blockIdx.x * G;

    const __half* Pattnh = g_pack + OFF_ATTNH;
    const __half* Pcomba = g_pack + OFF_COMBA;
    const __half* Pgih   = g_pack + OFF_GIH;
    const __half* Pghh   = g_pack + OFF_GHH;
    const __half* Pout   = g_pack + OFF_OUT;

    for (int i = tid; i < NL * G * Hh; i += NTH)
        (&s_h[0][0][0])[i] = 0.f;
    __syncthreads();

    for (int t = 0; t < Tt; t++) {
        // -------- token fetch (teacher forcing; SOS=0 at t=0) --------
        if (tid < G)
            s_tok[tid] = (t == 0) ? 0 : y[(b0 + tid) * Tt + t - 1];
        __syncthreads();

        // -------- attention scores: h-part split lo/hi K-halves; e-part from table ----
        {
            u64 acc[G] = {0, 0, 0, 0};
            const uint2* W = (const uint2*)Pattnh + (hi ? 32 * 256 : 0) + jj;
            const int kbase = hi ? 32 : 0;
            #pragma unroll 8
            for (int k4 = 0; k4 < 32; k4++) {
                uint2 wh = W[k4 * 256];
                u64 wx = cvt2(wh.x), wy = cvt2(wh.y);
                #pragma unroll
                for (int g = 0; g < G; g++) {
                    ulonglong2 xv = ((const ulonglong2*)(&s_h[0][g][0]))[kbase + k4];
                    fma2(acc[g], wx, xv.x);
                    fma2(acc[g], wy, xv.y);
                }
            }
            if (hi) {
                #pragma unroll
                for (int g = 0; g < G; g++) s_p2[g][0][jj] = sum2(acc[g]);
            }
            __syncthreads();

            // softmax over L per row (true values in lo half; table adds e-part+bias)
            float sc[G];
            #pragma unroll
            for (int g = 0; g < G; g++)
                sc[g] = hi ? -1e30f
                           : (sum2(acc[g]) + s_p2[g][0][jj] + g_Tattn[s_tok[g] * Ld + jj]);
            float m[G];
            #pragma unroll
            for (int g = 0; g < G; g++) m[g] = sc[g];
            block_reduce4(m, s_red, tid, true);
            float p[G];
            #pragma unroll
            for (int g = 0; g < G; g++) p[g] = hi ? 0.f : __expf(sc[g] - m[g]);
            float s[G];
            #pragma unroll
            for (int g = 0; g < G; g++) s[g] = p[g];
            block_reduce4(s, s_red, tid, false);
            if (!hi) {
                #pragma unroll
                for (int g = 0; g < G; g++) {
                    float a = p[g] * (1.f / s[g]);
                    s_aw[g][jj] = a;
                    attnp[((size_t)(b0 + g) * Tt + t) * Ld + jj] = a;
                }
            }
            __syncthreads();
        }

        // -------- applied = aw @ enc (fp16 enc, warp owns fixed row g) --------
        {
            const int g = wid >> 2;                    // 4 warps per batch row
            const int hbase = (wid & 3) * 64;          // 64 h-values per warp
            const float4* awp = (const float4*)(s_aw[g]);
            const float4 A0 = awp[lane * 2];
            const float4 A1 = awp[lane * 2 + 1];
            const uint4* xrow =
                (const uint4*)(g_enc + ((size_t)(b0 + g) * Hh + hbase) * Ld) + lane;
            #pragma unroll
            for (int it = 0; it < 64; it += 8) {
                uint4 xv[8];
                #pragma unroll
                for (int u = 0; u < 8; u++) xv[u] = xrow[(it + u) * 32];
                float d[8];
                #pragma unroll
                for (int u = 0; u < 8; u++) {
                    float2 f0 = __half22float2(*(__half2*)&xv[u].x);
                    float2 f1 = __half22float2(*(__half2*)&xv[u].y);
                    float2 f2 = __half22float2(*(__half2*)&xv[u].z);
                    float2 f3 = __half22float2(*(__half2*)&xv[u].w);
                    d[u] = f0.x * A0.x + f0.y * A0.y + f1.x * A0.z + f1.y * A0.w
                         + f2.x * A1.x + f2.y * A1.y + f3.x * A1.z + f3.y * A1.w;
                }
                #pragma unroll
                for (int u = 0; u < 8; u++) {
                    #pragma unroll
                    for (int o = 16; o > 0; o >>= 1)
                        d[u] += __shfl_xor_sync(0xffffffffu, d[u], o);
                }
                if (lane == 0) {
                    #pragma unroll
                    for (int u = 0; u < 8; u++) s_app[g][hbase + it + u] = d[u];
                }
            }
        }
        __syncthreads();

        // -------- combine: applied-part split lo/hi K-halves; e-part from table -------
        {
            u64 acc[G] = {0, 0, 0, 0};
            const uint2* W = (const uint2*)Pcomba + (hi ? 32 * 256 : 0) + jj;
            const int kbase = hi ? 32 : 0;
            #pragma unroll 8
            for (int k4 = 0; k4 < 32; k4++) {
                uint2 wh = W[k4 * 256];
                u64 wx = cvt2(wh.x), wy = cvt2(wh.y);
                #pragma unroll
                for (int g = 0; g < G; g++) {
                    ulonglong2 xv = ((const ulonglong2*)(&s_app[g][0]))[kbase + k4];
                    fma2(acc[g], wx, xv.x);
                    fma2(acc[g], wy, xv.y);
                }
            }
            if (hi) {
                #pragma unroll
                for (int g = 0; g < G; g++) s_p2[g][0][jj] = sum2(acc[g]);
            }
            __syncthreads();
            if (!hi) {
                #pragma unroll
                for (int g = 0; g < G; g++)
                    s_x[g][jj] = fmaxf(sum2(acc[g]) + s_p2[g][0][jj]
                                       + g_Tcomb[s_tok[g] * Hh + jj], 0.f);
            }
            __syncthreads();
        }

        // -------- GRU layers: lo half = ih matvec, hi half = hh matvec --------
        #pragma unroll
        for (int l = 0; l < NL; l++) {
            u64 a0[G] = {0,0,0,0}, a1[G] = {0,0,0,0}, a2[G] = {0,0,0,0};
            const uint2* W =
                (const uint2*)((hi ? Pghh : Pgih) + l * 196608) + jj;
            const float* vb = hi ? &s_h[l][0][0] : &s_x[0][0];
            #pragma unroll 4
            for (int k4 = 0; k4 < 64; k4++) {
                uint2 wh0 = W[k4 * 768];
                uint2 wh1 = W[k4 * 768 + 256];
                uint2 wh2 = W[k4 * 768 + 512];
                u64 w0x = cvt2(wh0.x), w0y = cvt2(wh0.y);
                u64 w1x = cvt2(wh1.x), w1y = cvt2(wh1.y);
                u64 w2x = cvt2(wh2.x), w2y = cvt2(wh2.y);
                #pragma unroll
                for (int g = 0; g < G; g++) {
                    ulonglong2 xv = ((const ulonglong2*)(vb + g * Hh))[k4];
                    fma2(a0[g], w0x, xv.x); fma2(a0[g], w0y, xv.y);
                    fma2(a1[g], w1x, xv.x); fma2(a1[g], w1y, xv.y);
                    fma2(a2[g], w2x, xv.x); fma2(a2[g], w2y, xv.y);
                }
            }
            if (hi) {
                #pragma unroll
                for (int g = 0; g < G; g++) {
                    s_p2[g][0][jj] = sum2(a0[g]);
                    s_p2[g][1][jj] = sum2(a1[g]);
                    s_p2[g][2][jj] = sum2(a2[g]);
                }
            }
            __syncthreads();
            if (!hi) {
                const float bi0 = gbi[l * 768 + jj];
                const float bi1 = gbi[l * 768 + 256 + jj];
                const float bi2 = gbi[l * 768 + 512 + jj];
                const float bh0 = gbh[l * 768 + jj];
                const float bh1 = gbh[l * 768 + 256 + jj];
                const float bh2 = gbh[l * 768 + 512 + jj];
                #pragma unroll
                for (int g = 0; g < G; g++) {
                    float hprev = s_h[l][g][jj];
                    float i0 = sum2(a0[g]) + bi0, h0 = s_p2[g][0][jj] + bh0;
                    float i1 = sum2(a1[g]) + bi1, h1 = s_p2[g][1][jj] + bh1;
                    float i2 = sum2(a2[g]) + bi2, h2 = s_p2[g][2][jj] + bh2;
                    float r = 1.f / (1.f + __expf(-(i0 + h0)));
                    float z = 1.f / (1.f + __expf(-(i1 + h1)));
                    float n = tanhf(i2 + r * h2);
                    float hn = (1.f - z) * n + z * hprev;
                    s_h[l][g][jj] = hn;
                    s_x[g][jj]    = hn;
                }
            }
            __syncthreads();
        }

        // -------- output projection (K split 4 ways) + log_softmax --------
        {
            int j  = tid & 127;
            int sl = tid >> 7;
            u64 acc[G] = {0, 0, 0, 0};
            const uint2* W = (const uint2*)Pout + j;
            #pragma unroll 8
            for (int k4 = sl * 16; k4 < sl * 16 + 16; k4++) {
                uint2 wh = W[k4 * 128];
                u64 wx = cvt2(wh.x), wy = cvt2(wh.y);
                #pragma unroll
                for (int g = 0; g < G; g++) {
                    ulonglong2 hv = ((const ulonglong2*)s_x[g])[k4];
                    fma2(acc[g], wx, hv.x);
                    fma2(acc[g], wy, hv.y);
                }
            }
            float* s_op = &s_p2[0][0][0];
            #pragma unroll
            for (int g = 0; g < G; g++) s_op[(g * 4 + sl) * 128 + j] = sum2(acc[g]);
            __syncthreads();

            float oacc[G];
            #pragma unroll
            for (int g = 0; g < G; g++) {
                oacc[g] = (tid < 128)
                    ? (out_b[j] + s_op[(g * 4 + 0) * 128 + j] + s_op[(g * 4 + 1) * 128 + j]
                               + s_op[(g * 4 + 2) * 128 + j] + s_op[(g * 4 + 3) * 128 + j])
                    : -1e30f;
            }
            float m[G];
            #pragma unroll
            for (int g = 0; g < G; g++) m[g] = oacc[g];
            block_reduce4(m, s_red, tid, true);
            float p[G];
            #pragma unroll
            for (int g = 0; g < G; g++) p[g] = (tid < 128) ? __expf(oacc[g] - m[g]) : 0.f;
            float s[G];
            #pragma unroll
            for (int g = 0; g < G; g++) s[g] = p[g];
            block_reduce4(s, s_red, tid, false);
            if (tid < 128) {
                #pragma unroll
                for (int g = 0; g < G; g++)
                    s_out[g][j][t & 7] = oacc[g] - m[g] - logf(s[g]);
            }
        }

        // -------- flush staged outputs every 8 steps (coalesced float4 x2) --------
        __syncthreads();
        if ((t & 7) == 7) {
            int g = tid >> 7, j = tid & 127;
            float4 v0 = *(float4*)&s_out[g][j][0];
            float4 v1 = *(float4*)&s_out[g][j][4];
            float4* dst = (float4*)(outp + ((size_t)(b0 + g) * Vv + j) * Tt + (t - 7));
            dst[0] = v0;
            dst[1] = v1;
            __syncthreads();
        }
    }
}

// ---------------- launch ----------------
extern "C" void kernel_launch(void* const* d_in, const int* in_sizes, int n_in,
                              void* d_out, int out_size)
{
    const float* x      = (const float*)d_in[0];
    const int*   y      = (const int*)  d_in[1];
    const float* emb    = (const float*)d_in[2];
    const float* attn_w = (const float*)d_in[3];
    const float* attn_b = (const float*)d_in[4];
    const float* comb_w = (const float*)d_in[5];
    const float* comb_b = (const float*)d_in[6];
    const float* gih    = (const float*)d_in[7];
    const float* ghh    = (const float*)d_in[8];
    const float* gbi    = (const float*)d_in[9];
    const float* gbh    = (const float*)d_in[10];
    const float* out_w  = (const float*)d_in[11];
    const float* out_b  = (const float*)d_in[12];

    float* outp  = (float*)d_out;                        // [B,V,T]
    float* attnp = (float*)d_out + (size_t)Bb * Vv * Tt; // [B,T,L]

    pack_all_kernel<<<PACK_BLOCKS + ENC_BLOCKS, 256>>>(attn_w, comb_w, gih, ghh, out_w, x);
    precompute_tok_kernel<<<2 * Vv, Hh>>>(emb, attn_w, attn_b, comb_w, comb_b);
    decoder_kernel<<<Bb / G, NTH>>>(y, gbi, gbh, out_b, outp, attnp);
}